// round 2
// baseline (speedup 1.0000x reference)
#include <cuda_runtime.h>
#include <cstdint>
#include <cstddef>

// diag[h][t], h in [0,4), t in [0,16)
__device__ float g_diag[64];

// ---------------------------------------------------------------------------
// Kernel 1: tiny attention -> softmax diagonal. One block per head.
// q = x @ Wq^T + bq ; k = y @ Wk^T + bk ; s = (q k^T) * 0.125 ; diag softmax row
// ---------------------------------------------------------------------------
__global__ void attn_diag_kernel(const float* __restrict__ x, const float* __restrict__ y,
                                 const float* __restrict__ Wq, const float* __restrict__ bq,
                                 const float* __restrict__ Wk, const float* __restrict__ bk)
{
    __shared__ float xs[4096], ys[4096];
    __shared__ float qs[1024], ks2[1024];   // [t][cl], cl in [0,64)
    __shared__ float sc[256];               // [i][j]
    const int h   = blockIdx.x;
    const int tid = threadIdx.x;

    for (int i = tid; i < 4096; i += 256) { xs[i] = x[i]; ys[i] = y[i]; }
    __syncthreads();

    const int lane = tid & 31, w = tid >> 5;
    for (int cc = 0; cc < 8; ++cc) {
        const int cl = w * 8 + cc;
        const int c  = h * 64 + cl;
        float aq[16], ak[16];
        #pragma unroll
        for (int t = 0; t < 16; ++t) { aq[t] = 0.f; ak[t] = 0.f; }
        #pragma unroll
        for (int i = 0; i < 8; ++i) {
            const int m = lane + 32 * i;
            const float wq = Wq[c * 256 + m];
            const float wk = Wk[c * 256 + m];
            #pragma unroll
            for (int t = 0; t < 16; ++t) {
                aq[t] += xs[t * 256 + m] * wq;
                ak[t] += ys[t * 256 + m] * wk;
            }
        }
        #pragma unroll
        for (int t = 0; t < 16; ++t) {
            float vq = aq[t], vk = ak[t];
            #pragma unroll
            for (int s = 16; s > 0; s >>= 1) {
                vq += __shfl_down_sync(0xffffffffu, vq, s);
                vk += __shfl_down_sync(0xffffffffu, vk, s);
            }
            if (lane == 0) {
                qs[t * 64 + cl]  = vq + bq[c];
                ks2[t * 64 + cl] = vk + bk[c];
            }
        }
    }
    __syncthreads();
    {
        const int i = tid >> 4, j = tid & 15;
        float s = 0.f;
        #pragma unroll 8
        for (int d = 0; d < 64; ++d) s += qs[i * 64 + d] * ks2[j * 64 + d];
        sc[tid] = s * 0.125f;   // SCALE = 64^-0.5
    }
    __syncthreads();
    if (tid < 16) {
        float mx = -1e30f;
        for (int j = 0; j < 16; ++j) mx = fmaxf(mx, sc[tid * 16 + j]);
        float sum = 0.f;
        for (int j = 0; j < 16; ++j) sum += expf(sc[tid * 16 + j] - mx);
        g_diag[h * 16 + tid] = expf(sc[tid * 16 + tid] - mx) / sum;
    }
}

// ---------------------------------------------------------------------------
// Kernel 2: fused permuted-gather GEMM + epilogue.
//
// Per slab (t, b): D[o, n] = sum_k Wo[o0+o, 4*d0+kk] * z[t, b*64+d, w0+wl, j*32+ab+al]
//   with kk = 4*dl + j, logical n = al*16 + wl  (al in [0,8), wl in [0,16))
// out[t,o,4*(ab+al)+b, w0+wl] = bo[o] + z[same] + diag[b][t] * D
//
// CTA tile M=128 (o), N=128, K streamed in 8 chunks of 32 via cp.async.
// mma.sync.m16n8k8 tf32.
// ---------------------------------------------------------------------------
#define AST 36          // A smem row stride (floats), conflict-free frag loads
#define BST 132         // B smem row stride per kk (floats), 16B-aligned rows
#define A_BUF 4608      // 128*36
#define B_BUF 4224      // 32*132
#define SMEM_FLOATS (2 * A_BUF + 2 * B_BUF)   // 17664 floats = 70656 B

__device__ __forceinline__ void cp16(float* dst, const float* src)
{
    unsigned s = (unsigned)__cvta_generic_to_shared(dst);
    asm volatile("cp.async.cg.shared.global [%0], [%1], 16;" :: "r"(s), "l"(src));
}

__global__ void __launch_bounds__(256, 2)
fuse_kernel(const float* __restrict__ z, const float* __restrict__ Wo,
            const float* __restrict__ bo, float* __restrict__ out)
{
    extern __shared__ float smem[];
    float* Abuf0 = smem;
    float* Abuf1 = smem + A_BUF;
    float* Bbuf0 = smem + 2 * A_BUF;
    float* Bbuf1 = smem + 2 * A_BUF + B_BUF;

    const int tid = threadIdx.x;
    const int bid = blockIdx.x;
    const int t   = bid >> 8;              // t-major for L2 reuse of z[t]
    const int b   = (bid >> 6) & 3;        // head / slab
    const int o0  = ((bid >> 5) & 1) << 7; // 0 or 128
    const int ab  = ((bid >> 3) & 3) << 3; // a base: 0,8,16,24
    const int w0  = (bid & 7) << 4;        // w' base: 0..112 step 16

    const float* zslab = z + ((size_t)(t * 256 + b * 64)) * 16384 + (size_t)w0 * 128 + ab;
    const float* Wob   = Wo + (size_t)o0 * 256;

    auto loadA = [&](int kc, float* Ab) {
        const int k0 = kc * 32;
        #pragma unroll
        for (int i = 0; i < 4; ++i) {
            const int L  = tid + i * 256;
            const int ol = L >> 3;
            const int f4 = (L & 7) << 2;
            cp16(Ab + ol * AST + f4, Wob + ol * 256 + k0 + f4);
        }
    };
    auto loadB = [&](int kc, float* Bb) {
        const int d0 = kc * 8;
        #pragma unroll
        for (int i = 0; i < 4; ++i) {
            const int L  = tid + i * 256;      // [0,1024)
            const int dl = L >> 7;             // 0..7
            const int wl = (L >> 3) & 15;      // 0..15
            const int jj = (L >> 1) & 3;       // 0..3
            const int a4 = (L & 1) << 2;       // 0 or 4
            cp16(Bb + (dl * 4 + jj) * BST + wl * 8 + a4,
                 zslab + (size_t)(d0 + dl) * 16384 + wl * 128 + jj * 32 + a4);
        }
    };

    const int lane = tid & 31;
    const int wrp  = tid >> 5;
    const int wm   = (wrp & 1) * 64;       // warp M offset
    const int wn   = (wrp >> 1) * 32;      // warp N offset
    const int grp  = lane >> 2;            // 0..7
    const int qid  = lane & 3;             // 0..3

    float acc[4][4][4];
    #pragma unroll
    for (int i = 0; i < 4; ++i)
        #pragma unroll
        for (int j = 0; j < 4; ++j)
            #pragma unroll
            for (int r = 0; r < 4; ++r) acc[i][j][r] = 0.f;

    int rowbase[4];
    #pragma unroll
    for (int mt = 0; mt < 4; ++mt) rowbase[mt] = (wm + mt * 16 + grp) * AST;
    int boff[4];
    #pragma unroll
    for (int nt = 0; nt < 4; ++nt) {
        const int n = wn + nt * 8 + grp;               // logical n = al*16 + wl
        boff[nt] = (n & 15) * 8 + (n >> 4);            // physical [kk][wl][al]
    }

    loadA(0, Abuf0); loadB(0, Bbuf0);
    asm volatile("cp.async.commit_group;");

    for (int kc = 0; kc < 8; ++kc) {
        float* Ab = (kc & 1) ? Abuf1 : Abuf0;
        float* Bb = (kc & 1) ? Bbuf1 : Bbuf0;
        if (kc < 7) {
            float* An = (kc & 1) ? Abuf0 : Abuf1;
            float* Bn = (kc & 1) ? Bbuf0 : Bbuf1;
            loadA(kc + 1, An); loadB(kc + 1, Bn);
            asm volatile("cp.async.commit_group;");
            asm volatile("cp.async.wait_group 1;");
        } else {
            asm volatile("cp.async.wait_group 0;");
        }
        __syncthreads();

        #pragma unroll
        for (int ks = 0; ks < 4; ++ks) {
            const int kf = ks * 8;
            uint32_t afr[4][4];
            #pragma unroll
            for (int mt = 0; mt < 4; ++mt) {
                afr[mt][0] = __float_as_uint(Ab[rowbase[mt] + kf + qid]);
                afr[mt][1] = __float_as_uint(Ab[rowbase[mt] + 8 * AST + kf + qid]);
                afr[mt][2] = __float_as_uint(Ab[rowbase[mt] + kf + qid + 4]);
                afr[mt][3] = __float_as_uint(Ab[rowbase[mt] + 8 * AST + kf + qid + 4]);
            }
            uint32_t bfr[4][2];
            #pragma unroll
            for (int nt = 0; nt < 4; ++nt) {
                bfr[nt][0] = __float_as_uint(Bb[(kf + qid) * BST + boff[nt]]);
                bfr[nt][1] = __float_as_uint(Bb[(kf + 4 + qid) * BST + boff[nt]]);
            }
            #pragma unroll
            for (int mt = 0; mt < 4; ++mt)
                #pragma unroll
                for (int nt = 0; nt < 4; ++nt) {
                    asm volatile(
                        "mma.sync.aligned.m16n8k8.row.col.f32.tf32.tf32.f32 "
                        "{%0,%1,%2,%3}, {%4,%5,%6,%7}, {%8,%9}, {%0,%1,%2,%3};"
                        : "+f"(acc[mt][nt][0]), "+f"(acc[mt][nt][1]),
                          "+f"(acc[mt][nt][2]), "+f"(acc[mt][nt][3])
                        : "r"(afr[mt][0]), "r"(afr[mt][1]),
                          "r"(afr[mt][2]), "r"(afr[mt][3]),
                          "r"(bfr[nt][0]), "r"(bfr[nt][1]));
                }
        }
        __syncthreads();
    }

    // Epilogue: out = bo + z + diag * acc ; float2 stores on adjacent w'
    const float dg = g_diag[b * 16 + t];
    #pragma unroll
    for (int mt = 0; mt < 4; ++mt) {
        #pragma unroll
        for (int half = 0; half < 2; ++half) {
            const int o = o0 + wm + mt * 16 + grp + half * 8;
            const float bov = bo[o];
            const size_t obase = (size_t)(t * 256 + o) * 16384;
            #pragma unroll
            for (int nt = 0; nt < 4; ++nt) {
                const int ncol = wn + nt * 8 + 2 * qid;   // even, pair stays in same al
                const int al = ncol >> 4;
                const int wl = ncol & 15;
                const int hp = (ab + al) * 4 + b;
                const size_t off = obase + (size_t)hp * 128 + (w0 + wl);
                const float2 zr = *reinterpret_cast<const float2*>(z + off);
                float2 r;
                r.x = bov + zr.x + dg * acc[mt][nt][half * 2 + 0];
                r.y = bov + zr.y + dg * acc[mt][nt][half * 2 + 1];
                *reinterpret_cast<float2*>(out + off) = r;
            }
        }
    }
}

// ---------------------------------------------------------------------------
extern "C" void kernel_launch(void* const* d_in, const int* in_sizes, int n_in,
                              void* d_out, int out_size)
{
    (void)in_sizes; (void)n_in; (void)out_size;
    const float* x  = (const float*)d_in[0];
    const float* y  = (const float*)d_in[1];
    const float* z  = (const float*)d_in[2];
    const float* Wq = (const float*)d_in[3];
    const float* bq = (const float*)d_in[4];
    const float* Wk = (const float*)d_in[5];
    const float* bk = (const float*)d_in[6];
    const float* Wo = (const float*)d_in[7];
    const float* bo = (const float*)d_in[8];
    float* out = (float*)d_out;

    cudaFuncSetAttribute(fuse_kernel, cudaFuncAttributeMaxDynamicSharedMemorySize,
                         SMEM_FLOATS * 4);

    attn_diag_kernel<<<4, 256>>>(x, y, Wq, bq, Wk, bk);
    fuse_kernel<<<4096, 256, SMEM_FLOATS * 4>>>(z, Wo, bo, out);
}

// round 3
// speedup vs baseline: 1.3046x; 1.3046x over previous
#include <cuda_runtime.h>
#include <cuda_bf16.h>
#include <cstdint>
#include <cstddef>

// diag[h][t], h in [0,4), t in [0,16)
__device__ float g_diag[64];
// Wo converted to bf16, [o][k] row-major, 256x256
__device__ __nv_bfloat16 g_wo[65536];

// ---------------------------------------------------------------------------
// Kernel 1: tiny attention -> softmax diagonal. One block per head.
// ---------------------------------------------------------------------------
__global__ void attn_diag_kernel(const float* __restrict__ x, const float* __restrict__ y,
                                 const float* __restrict__ Wq, const float* __restrict__ bq,
                                 const float* __restrict__ Wk, const float* __restrict__ bk)
{
    __shared__ float xs[4096], ys[4096];
    __shared__ float qs[1024], ks2[1024];
    __shared__ float sc[256];
    const int h   = blockIdx.x;
    const int tid = threadIdx.x;

    for (int i = tid; i < 4096; i += 256) { xs[i] = x[i]; ys[i] = y[i]; }
    __syncthreads();

    const int lane = tid & 31, w = tid >> 5;
    for (int cc = 0; cc < 8; ++cc) {
        const int cl = w * 8 + cc;
        const int c  = h * 64 + cl;
        float aq[16], ak[16];
        #pragma unroll
        for (int t = 0; t < 16; ++t) { aq[t] = 0.f; ak[t] = 0.f; }
        #pragma unroll
        for (int i = 0; i < 8; ++i) {
            const int m = lane + 32 * i;
            const float wq = Wq[c * 256 + m];
            const float wk = Wk[c * 256 + m];
            #pragma unroll
            for (int t = 0; t < 16; ++t) {
                aq[t] += xs[t * 256 + m] * wq;
                ak[t] += ys[t * 256 + m] * wk;
            }
        }
        #pragma unroll
        for (int t = 0; t < 16; ++t) {
            float vq = aq[t], vk = ak[t];
            #pragma unroll
            for (int s = 16; s > 0; s >>= 1) {
                vq += __shfl_down_sync(0xffffffffu, vq, s);
                vk += __shfl_down_sync(0xffffffffu, vk, s);
            }
            if (lane == 0) {
                qs[t * 64 + cl]  = vq + bq[c];
                ks2[t * 64 + cl] = vk + bk[c];
            }
        }
    }
    __syncthreads();
    {
        const int i = tid >> 4, j = tid & 15;
        float s = 0.f;
        #pragma unroll 8
        for (int d = 0; d < 64; ++d) s += qs[i * 64 + d] * ks2[j * 64 + d];
        sc[tid] = s * 0.125f;
    }
    __syncthreads();
    if (tid < 16) {
        float mx = -1e30f;
        for (int j = 0; j < 16; ++j) mx = fmaxf(mx, sc[tid * 16 + j]);
        float sum = 0.f;
        for (int j = 0; j < 16; ++j) sum += expf(sc[tid * 16 + j] - mx);
        g_diag[h * 16 + tid] = expf(sc[tid * 16 + tid] - mx) / sum;
    }
}

// ---------------------------------------------------------------------------
// Kernel 1b: Wo fp32 -> bf16 (one-time, 64K elements)
// ---------------------------------------------------------------------------
__global__ void convert_wo_kernel(const float* __restrict__ Wo)
{
    const int i = blockIdx.x * 256 + threadIdx.x;
    g_wo[i] = __float2bfloat16(Wo[i]);
}

// ---------------------------------------------------------------------------
// Kernel 2: fused permuted-gather bf16 GEMM + epilogue.
// Per CTA (t, b, o0, ab, w0): D[o(128), n(128)] over K=256, 4 chunks of 64.
//   k-local = 4*dl + jj (dl in [0,16), jj in [0,4)), global c' = kc*64 + klocal
//   n = al*16 + wl (al in [0,8), wl in [0,16))
//   B[k][n] = z[t, b*64 + kc*16 + dl, w0+wl, ab + jj*32 + al]
// Smem: fp32 staging (cp.async target) -> converted to XOR-swizzled bf16 tiles,
// fragments via ldmatrix.x4 (A) / ldmatrix.x4.trans (B), mma m16n8k16 bf16.
// ---------------------------------------------------------------------------
#define SMEM_BYTES 98304   // 32KB stg + 2x16KB A + 2x16KB B

__device__ __forceinline__ void cp16(uint32_t dst, const void* src)
{
    asm volatile("cp.async.cg.shared.global [%0], [%1], 16;" :: "r"(dst), "l"(src));
}

__global__ void __launch_bounds__(256, 2)
fuse_kernel(const float* __restrict__ z, const float* __restrict__ bo,
            float* __restrict__ out)
{
    extern __shared__ char smem[];
    float* stg = (float*)smem;                                   // [dl][jj][wl][al]
    __nv_bfloat16* Bbuf = (__nv_bfloat16*)(smem + 65536);

    const int tid = threadIdx.x;
    const int bid = blockIdx.x;
    const int t   = bid >> 8;              // t-major for L2 reuse of z[t]
    const int b   = (bid >> 6) & 3;
    const int o0  = ((bid >> 5) & 1) << 7;
    const int ab  = ((bid >> 3) & 3) << 3;
    const int w0  = (bid & 7) << 4;

    const float* zslab = z + (size_t)(t * 256 + b * 64) * 16384 + (size_t)w0 * 128 + ab;

    const uint32_t stg_s  = (uint32_t)__cvta_generic_to_shared(smem);
    const uint32_t abuf_s = stg_s + 32768;
    const uint32_t bbuf_s = stg_s + 65536;

    // ---- async fill: z fp32 gather -> staging; Wo bf16 -> A tile ----
    auto fillStg = [&](int kc) {
        #pragma unroll
        for (int i = 0; i < 8; ++i) {
            const int L  = tid + i * 256;
            const int hf = L & 1, jj = (L >> 1) & 3, wl = (L >> 3) & 15, dl = L >> 7;
            const float* src = zslab + (size_t)(kc * 16 + dl) * 16384 + wl * 128 + jj * 32 + hf * 4;
            cp16(stg_s + (uint32_t)((((dl * 4 + jj) * 16 + wl) * 8 + hf * 4) * 4), src);
        }
    };
    auto fillA = [&](int kc, int buf) {
        const uint32_t base = abuf_s + buf * 16384;
        const __nv_bfloat16* wsrc = g_wo + (size_t)o0 * 256 + kc * 64;
        #pragma unroll
        for (int i = 0; i < 4; ++i) {
            const int L = tid + i * 256;
            const int row = L >> 3, g = L & 7;
            cp16(base + (uint32_t)((row * 64 + ((g ^ (row & 7)) * 8)) * 2),
                 wsrc + row * 256 + g * 8);
        }
    };
    // ---- convert staging fp32 -> swizzled bf16 B tile [k(64)][n(128)] ----
    auto convertB = [&](int buf) {
        __nv_bfloat16* bb = Bbuf + buf * 8192;
        #pragma unroll
        for (int i = 0; i < 4; ++i) {
            const int u  = tid + i * 256;
            const int h  = u & 1, al = (u >> 1) & 7, jj = (u >> 4) & 3, dl = u >> 6;
            const int k  = dl * 4 + jj;
            const float* sp = stg + ((dl * 4 + jj) * 16 + 8 * h) * 8 + al;
            float f[8];
            #pragma unroll
            for (int r = 0; r < 8; ++r) f[r] = sp[r * 8];
            uint32_t p[4];
            #pragma unroll
            for (int r = 0; r < 4; ++r)
                asm("cvt.rn.bf16x2.f32 %0, %1, %2;" : "=r"(p[r]) : "f"(f[2*r+1]), "f"(f[2*r]));
            const int gn = al * 2 + h;                 // n-granule (8 n per granule)
            uint32_t dst = bbuf_s + buf * 16384 + (uint32_t)((k * 128 + ((gn ^ (k & 7)) * 8)) * 2);
            asm volatile("st.shared.v4.b32 [%0], {%1,%2,%3,%4};"
                         :: "r"(dst), "r"(p[0]), "r"(p[1]), "r"(p[2]), "r"(p[3]));
        }
        (void)bb;
    };

    const int lane = tid & 31;
    const int wrp  = tid >> 5;
    const int wm   = (wrp & 1) * 64;       // warp M offset
    const int wn   = (wrp >> 1) * 32;      // warp N offset
    const int grp  = lane >> 2;
    const int qid  = lane & 3;
    const int l16  = lane & 15;
    const int lhi  = lane >> 4;

    float acc[4][4][4];
    #pragma unroll
    for (int i = 0; i < 4; ++i)
        #pragma unroll
        for (int j = 0; j < 4; ++j)
            #pragma unroll
            for (int r = 0; r < 4; ++r) acc[i][j][r] = 0.f;

    fillA(0, 0); fillStg(0);
    asm volatile("cp.async.commit_group;");
    asm volatile("cp.async.wait_group 0;");
    __syncthreads();

    #pragma unroll 1
    for (int kc = 0; kc < 4; ++kc) {
        const int cur = kc & 1;
        convertB(cur);
        __syncthreads();
        if (kc < 3) {
            fillA(kc + 1, cur ^ 1);
            fillStg(kc + 1);
            asm volatile("cp.async.commit_group;");
        }

        const uint32_t abase = abuf_s + cur * 16384;
        const uint32_t bbase = bbuf_s + cur * 16384;

        #pragma unroll
        for (int ks = 0; ks < 4; ++ks) {
            uint32_t afr[4][4];
            #pragma unroll
            for (int mt = 0; mt < 4; ++mt) {
                const int row = wm + mt * 16 + l16;
                const int g   = (2 * ks + lhi) ^ (row & 7);
                const uint32_t addr = abase + (uint32_t)((row * 64 + g * 8) * 2);
                asm volatile("ldmatrix.sync.aligned.m8n8.x4.shared.b16 {%0,%1,%2,%3}, [%4];"
                             : "=r"(afr[mt][0]), "=r"(afr[mt][1]),
                               "=r"(afr[mt][2]), "=r"(afr[mt][3])
                             : "r"(addr));
            }
            uint32_t bfr[4][2];
            #pragma unroll
            for (int p = 0; p < 2; ++p) {
                const int k  = ks * 16 + l16;
                const int gn = ((wn >> 3) + 2 * p + lhi) ^ (k & 7);
                const uint32_t addr = bbase + (uint32_t)((k * 128 + gn * 8) * 2);
                asm volatile("ldmatrix.sync.aligned.m8n8.x4.trans.shared.b16 {%0,%1,%2,%3}, [%4];"
                             : "=r"(bfr[2*p][0]), "=r"(bfr[2*p][1]),
                               "=r"(bfr[2*p+1][0]), "=r"(bfr[2*p+1][1])
                             : "r"(addr));
            }
            #pragma unroll
            for (int mt = 0; mt < 4; ++mt)
                #pragma unroll
                for (int nt = 0; nt < 4; ++nt) {
                    asm volatile(
                        "mma.sync.aligned.m16n8k16.row.col.f32.bf16.bf16.f32 "
                        "{%0,%1,%2,%3}, {%4,%5,%6,%7}, {%8,%9}, {%0,%1,%2,%3};"
                        : "+f"(acc[mt][nt][0]), "+f"(acc[mt][nt][1]),
                          "+f"(acc[mt][nt][2]), "+f"(acc[mt][nt][3])
                        : "r"(afr[mt][0]), "r"(afr[mt][1]),
                          "r"(afr[mt][2]), "r"(afr[mt][3]),
                          "r"(bfr[nt][0]), "r"(bfr[nt][1]));
                }
        }

        if (kc < 3) {
            asm volatile("cp.async.wait_group 0;");
            __syncthreads();
        }
    }

    // ---- Epilogue: out = bo + z + diag * acc ; float2 stores along w ----
    const float dg = g_diag[b * 16 + t];
    #pragma unroll
    for (int mt = 0; mt < 4; ++mt) {
        #pragma unroll
        for (int half = 0; half < 2; ++half) {
            const int o = o0 + wm + mt * 16 + grp + half * 8;
            const float bov = bo[o];
            const size_t obase = (size_t)(t * 256 + o) * 16384;
            #pragma unroll
            for (int nt = 0; nt < 4; ++nt) {
                const int ncol = wn + nt * 8 + 2 * qid;   // even; pair stays in same al
                const int al = ncol >> 4;
                const int wl = ncol & 15;
                const int hp = (ab + al) * 4 + b;
                const size_t off = obase + (size_t)hp * 128 + (w0 + wl);
                const float2 zr = *reinterpret_cast<const float2*>(z + off);
                float2 r;
                r.x = bov + zr.x + dg * acc[mt][nt][half * 2 + 0];
                r.y = bov + zr.y + dg * acc[mt][nt][half * 2 + 1];
                *reinterpret_cast<float2*>(out + off) = r;
            }
        }
    }
}

// ---------------------------------------------------------------------------
extern "C" void kernel_launch(void* const* d_in, const int* in_sizes, int n_in,
                              void* d_out, int out_size)
{
    (void)in_sizes; (void)n_in; (void)out_size;
    const float* x  = (const float*)d_in[0];
    const float* y  = (const float*)d_in[1];
    const float* z  = (const float*)d_in[2];
    const float* Wq = (const float*)d_in[3];
    const float* bq = (const float*)d_in[4];
    const float* Wk = (const float*)d_in[5];
    const float* bk = (const float*)d_in[6];
    const float* Wo = (const float*)d_in[7];
    const float* bo = (const float*)d_in[8];
    float* out = (float*)d_out;

    cudaFuncSetAttribute(fuse_kernel, cudaFuncAttributeMaxDynamicSharedMemorySize,
                         SMEM_BYTES);

    attn_diag_kernel<<<4, 256>>>(x, y, Wq, bq, Wk, bk);
    convert_wo_kernel<<<256, 256>>>(Wo);
    fuse_kernel<<<4096, 256, SMEM_BYTES>>>(z, bo, out);
}